// round 13
// baseline (speedup 1.0000x reference)
#include <cuda_runtime.h>

// ---------------------------------------------------------------------------
// Problem constants
// ---------------------------------------------------------------------------
#define HH   8
#define DD   128
#define KDD  16
#define EE   128
#define BB   16
#define GG   501
#define NPP  250
#define NTOK (BB*GG)      // 8016
#define NHALF (BB*NPP)    // 4000
#define SCALE2 0.3606737602222409f   // (1/sqrt(16)) * log2(e)

typedef unsigned long long ull;

// ---------------------------------------------------------------------------
// Scratch
// ---------------------------------------------------------------------------
__device__ float g_qT[DD*NTOK];            // transposed input: [d][token]
__device__ float g_Q[HH*NTOK*KDD];
__device__ float g_K[HH*NTOK*KDD];
__device__ float g_V[HH*NTOK*KDD];
// [0]=W1(pick single) [1]=W2(pick vs K_pick) [2]=W3(pick vs K_del)
// [3]=W4(del single)  [4]=W5(del vs K_del)   [5]=W6(del vs K_pick)
__device__ float g_EQ[6][HH*NHALF*KDD];
__device__ float g_pacc[4][HH*NTOK*KDD];   // partial sum(w*V) per key-quarter
__device__ float g_pl[4][HH*NTOK];         // partial sum(w)   per key-quarter
__device__ float g_headsT[NTOK*HH*KDD];    // combined heads, token-major [tok][hk]

struct WArgs { const float* w[9]; };

// ---------------------------------------------------------------------------
// Packed fp32x2 helpers
// ---------------------------------------------------------------------------
__device__ __forceinline__ ull mul2(ull a, ull b) {
    ull r; asm("mul.rn.f32x2 %0,%1,%2;" : "=l"(r) : "l"(a), "l"(b)); return r;
}
__device__ __forceinline__ void fma2(ull& d, ull a, ull b) {
    asm("fma.rn.f32x2 %0,%1,%2,%0;" : "+l"(d) : "l"(a), "l"(b));
}
__device__ __forceinline__ ull add2(ull a, ull b) {
    ull r; asm("add.rn.f32x2 %0,%1,%2;" : "=l"(r) : "l"(a), "l"(b)); return r;
}
__device__ __forceinline__ ull pk2(float lo, float hi) {
    ull r; asm("mov.b64 %0,{%1,%2};" : "=l"(r) : "f"(lo), "f"(hi)); return r;
}
__device__ __forceinline__ float2 up2(ull a) {
    float lo, hi; asm("mov.b64 {%0,%1},%2;" : "=f"(lo), "=f"(hi) : "l"(a));
    return make_float2(lo, hi);
}
__device__ __forceinline__ float ex2(float x) {
    float r; asm("ex2.approx.f32 %0, %1;" : "=f"(r) : "f"(x)); return r;
}

// ---------------------------------------------------------------------------
// Kernel 0: transpose q [token][d] -> g_qT [d][token]. 32x32 tiles.
// ---------------------------------------------------------------------------
__global__ void transpose_kernel(const float* __restrict__ q) {
    __shared__ float s[32][33];
    const int t0 = blockIdx.x * 32;
    const int d0 = blockIdx.y * 32;
    const int x = threadIdx.x, y = threadIdx.y;   // block (32,8)
#pragma unroll
    for (int j = 0; j < 32; j += 8) {
        int t = t0 + y + j;
        s[y+j][x] = (t < NTOK) ? q[(size_t)t*DD + d0 + x] : 0.f;
    }
    __syncthreads();
#pragma unroll
    for (int j = 0; j < 32; j += 8) {
        int t = t0 + x;
        if (t < NTOK) g_qT[(size_t)(d0 + y + j)*NTOK + t] = s[x][y+j];
    }
}

// ---------------------------------------------------------------------------
// Kernel 1: projections as folded GEMMs, d-major q tile.
// Tile 128 rows x 64 cols, 256 threads, thread = 8 rows (4 pairs) x 4 cols.
// ---------------------------------------------------------------------------
__global__ void __launch_bounds__(256, 2) proj_kernel(WArgs a) {
    extern __shared__ float sm[];
    float* qsT = sm;              // 128 d x 128 rows
    float* ws  = sm + 128*128;    // 128 d x 64 cols

    int bx = blockIdx.x;
    const int ch = blockIdx.y;    // column half (0/1)
    int job, tile;
    if (bx < 189) { job = bx / 63; tile = bx % 63; }
    else          { bx -= 189; job = 3 + bx / 32; tile = bx % 32; }

    const bool full = (job < 3);
    const int nrows = full ? NTOK : NHALF;
    const int r0 = tile * 128;
    const int tid = threadIdx.x;

    {
        const float4* W4 = (const float4*)a.w[job];
        float4* ws4 = (float4*)ws;
        for (int i = tid; i < DD*16; i += 256) {
            int d = i >> 4, c4 = i & 15;
            int gc4 = ch*16 + c4;
            ws4[i] = W4[(gc4 >> 2)*(DD*4) + d*4 + (gc4 & 3)];
        }
    }

    if (full) {
        float4* q4 = (float4*)qsT;
        for (int i = tid; i < 128*32; i += 256) {
            int d = i >> 5, r4 = i & 31;
            int t = r0 + r4*4;
            float4 v = make_float4(0.f, 0.f, 0.f, 0.f);
            if (t < NTOK) v = *(const float4*)(g_qT + (size_t)d*NTOK + t);
            q4[d*32 + r4] = v;
        }
    } else {
        const int off = (job < 6) ? 1 : (NPP + 1);
        for (int i = tid; i < 128*128; i += 256) {
            int d = i >> 7, r = i & 127;
            int rt = r0 + r;
            float v = 0.f;
            if (rt < NHALF) {
                int b = rt / NPP, p = rt % NPP;
                v = g_qT[(size_t)d*NTOK + b*GG + off + p];
            }
            qsT[d*128 + r] = v;
        }
    }
    __syncthreads();

    const int cg = tid & 15;
    const int rg = tid >> 4;

    ull acc[4][4];
#pragma unroll
    for (int p = 0; p < 4; p++)
#pragma unroll
        for (int c = 0; c < 4; c++) acc[p][c] = 0ull;

#pragma unroll 4
    for (int d = 0; d < DD; d++) {
        const float* qb = qsT + d*128 + rg*8;
        ulonglong2 qa = *(const ulonglong2*)(qb);
        ulonglong2 qc = *(const ulonglong2*)(qb + 4);
        float4 w = *(const float4*)(ws + d*64 + cg*4);
        ull w0 = pk2(w.x, w.x), w1 = pk2(w.y, w.y);
        ull w2 = pk2(w.z, w.z), w3 = pk2(w.w, w.w);
        fma2(acc[0][0], qa.x, w0); fma2(acc[0][1], qa.x, w1);
        fma2(acc[0][2], qa.x, w2); fma2(acc[0][3], qa.x, w3);
        fma2(acc[1][0], qa.y, w0); fma2(acc[1][1], qa.y, w1);
        fma2(acc[1][2], qa.y, w2); fma2(acc[1][3], qa.y, w3);
        fma2(acc[2][0], qc.x, w0); fma2(acc[2][1], qc.x, w1);
        fma2(acc[2][2], qc.x, w2); fma2(acc[2][3], qc.x, w3);
        fma2(acc[3][0], qc.y, w0); fma2(acc[3][1], qc.y, w1);
        fma2(acc[3][2], qc.y, w2); fma2(acc[3][3], qc.y, w3);
    }

    float* outp;
    if      (job == 0) outp = g_Q;
    else if (job == 1) outp = g_K;
    else if (job == 2) outp = g_V;
    else               outp = g_EQ[job-3];

    const int gcol0 = ch*64 + cg*4;
    const int h  = gcol0 >> 4;
    const int k0 = gcol0 & 15;
#pragma unroll
    for (int p = 0; p < 4; p++) {
        float2 c0 = up2(acc[p][0]), c1 = up2(acc[p][1]);
        float2 c2 = up2(acc[p][2]), c3 = up2(acc[p][3]);
        int rlo = r0 + rg*8 + 2*p;
        if (rlo < nrows) {
            float* o = outp + ((size_t)h*nrows + rlo)*KDD + k0;
            *(float4*)o = make_float4(c0.x, c1.x, c2.x, c3.x);
        }
        if (rlo + 1 < nrows) {
            float* o = outp + ((size_t)h*nrows + rlo + 1)*KDD + k0;
            *(float4*)o = make_float4(c0.y, c1.y, c2.y, c3.y);
        }
    }
}

// ---------------------------------------------------------------------------
// Attention helpers. K/V row = 16 floats = 4 ulonglong2.
// ---------------------------------------------------------------------------
__device__ __forceinline__ float dotp(const ull* qp,
        ulonglong2 ka, ulonglong2 kb, ulonglong2 kc, ulonglong2 kd) {
    ull p0 = mul2(qp[0], ka.x);
    ull p1 = mul2(qp[1], ka.y);
    fma2(p0, qp[2], kb.x); fma2(p1, qp[3], kb.y);
    fma2(p0, qp[4], kc.x); fma2(p1, qp[5], kc.y);
    fma2(p0, qp[6], kd.x); fma2(p1, qp[7], kd.y);
    float2 s = up2(add2(p0, p1));
    return s.x + s.y;
}

__device__ __forceinline__ void accum(float w, ull* acc, float& l,
        ulonglong2 va, ulonglong2 vb, ulonglong2 vc, ulonglong2 vd) {
    l += w;
    ull wp = pk2(w, w);
    fma2(acc[0], wp, va.x); fma2(acc[1], wp, va.y);
    fma2(acc[2], wp, vb.x); fma2(acc[3], wp, vb.y);
    fma2(acc[4], wp, vc.x); fma2(acc[5], wp, vc.y);
    fma2(acc[6], wp, vd.x); fma2(acc[7], wp, vd.y);
}

__device__ __forceinline__ void attn_key2(const ulonglong2* KsU, const ulonglong2* VsU,
        int j,
        const ull* qp0, bool a0, float& l0, ull* acc0,
        const ull* qp1, bool a1, float& l1, ull* acc1) {
    ulonglong2 ka = KsU[j*4+0], kb = KsU[j*4+1], kc = KsU[j*4+2], kd = KsU[j*4+3];
    float s0 = dotp(qp0, ka, kb, kc, kd);
    float s1 = dotp(qp1, ka, kb, kc, kd);
    float w0 = a0 ? ex2(s0) : 0.f;
    float w1 = a1 ? ex2(s1) : 0.f;
    ulonglong2 va = VsU[j*4+0], vb = VsU[j*4+1], vc = VsU[j*4+2], vd = VsU[j*4+3];
    accum(w0, acc0, l0, va, vb, vc, vd);
    accum(w1, acc1, l1, va, vb, vc, vd);
}

__device__ __forceinline__ void loadq(const float* src, ull* qp) {
    const float4* s4 = (const float4*)src;
#pragma unroll
    for (int t = 0; t < 4; t++) {
        float4 v = s4[t];
        qp[2*t]   = pk2(v.x*SCALE2, v.y*SCALE2);
        qp[2*t+1] = pk2(v.z*SCALE2, v.w*SCALE2);
    }
}

// ---------------------------------------------------------------------------
// Kernel 2: attention split over key QUARTERS.
// grid (HB=128, 2 qchunks, 4 key-quarters), block 128, 2 queries/thread.
// ---------------------------------------------------------------------------
__global__ void __launch_bounds__(128, 4) attn_kernel() {
    extern __shared__ float sm[];
    const ulonglong2* KsU = (const ulonglong2*)sm;        // 126 rows * 4
    const ulonglong2* VsU = KsU + 126*4;

    const int hb  = blockIdx.x;
    const int tid = threadIdx.x;
    const int z   = blockIdx.z;
    const int kstart = (z==0) ? 0 : (z==1) ? 126 : (z==2) ? 251 : 376;
    const int nk     = (z==0) ? 126 : 125;

    {
        const float4* K4 = (const float4*)(g_K + ((size_t)hb*GG + kstart)*KDD);
        const float4* V4 = (const float4*)(g_V + ((size_t)hb*GG + kstart)*KDD);
        float4* Ks4 = (float4*)sm;
        float4* Vs4 = Ks4 + 126*4;
        for (int i = tid; i < nk*4; i += 128) {
            Ks4[i] = K4[i];
            Vs4[i] = V4[i];
        }
    }
    __syncthreads();

    const int base = blockIdx.y * 256;
    const int n0 = base + tid;
    const int n1 = base + 128 + tid;
    const bool v0 = (n0 < GG);
    const bool v1 = (n1 < GG);
    const int nn0 = v0 ? n0 : 0;
    const int nn1 = v1 ? n1 : 0;

    ull qp0[8], qp1[8], acc0[8], acc1[8];
    float l0 = 0.f, l1 = 0.f;
#pragma unroll
    for (int k = 0; k < 8; k++) { acc0[k] = 0ull; acc1[k] = 0ull; }
    loadq(g_Q + ((size_t)hb*GG + nn0)*KDD, qp0);
    loadq(g_Q + ((size_t)hb*GG + nn1)*KDD, qp1);

    for (int j = 0; j < nk; j++)
        attn_key2(KsU, VsU, j, qp0, true, l0, acc0, qp1, true, l1, acc1);

    const bool pk0 = (n0 >= 1) && (n0 <= NPP);
    const bool dl0 = (n0 >= NPP+1) && (n0 < GG);
    const bool ex0 = pk0 || dl0;
    const int  p0  = pk0 ? (n0-1) : (n0-NPP-1);
    const bool pk1 = (n1 >= 1) && (n1 <= NPP);
    const bool dl1 = (n1 >= NPP+1) && (n1 < GG);
    const bool ex1 = pk1 || dl1;
    const int  p1  = pk1 ? (n1-1) : (n1-NPP-1);

    {
        const float* e0src = (z < 2) ? (pk0 ? g_EQ[1] : g_EQ[5]) : (pk0 ? g_EQ[2] : g_EQ[4]);
        const float* e1src = (z < 2) ? (pk1 ? g_EQ[1] : g_EQ[5]) : (pk1 ? g_EQ[2] : g_EQ[4]);
        if (ex0) loadq(e0src + ((size_t)hb*NPP + p0)*KDD, qp0);
        if (ex1) loadq(e1src + ((size_t)hb*NPP + p1)*KDD, qp1);
        const int st = (z == 0) ? 1 : 0;
        for (int j = st; j < st + 125; j++)
            attn_key2(KsU, VsU, j, qp0, ex0, l0, acc0, qp1, ex1, l1, acc1);
    }

    {
        const bool c0 = (z < 2) ? dl0 : pk0;
        const bool c1 = (z < 2) ? dl1 : pk1;
        const float* psrc = (z < 2) ? g_EQ[3] : g_EQ[0];
        if (c0) {
            int keyg = ((z < 2) ? 1 : 251) + p0;
            int loc = keyg - kstart;
            if (loc >= 0 && loc < nk) {
                loadq(psrc + ((size_t)hb*NPP + p0)*KDD, qp0);
                float w = ex2(dotp(qp0, KsU[loc*4+0], KsU[loc*4+1], KsU[loc*4+2], KsU[loc*4+3]));
                accum(w, acc0, l0, VsU[loc*4+0], VsU[loc*4+1], VsU[loc*4+2], VsU[loc*4+3]);
            }
        }
        if (c1) {
            int keyg = ((z < 2) ? 1 : 251) + p1;
            int loc = keyg - kstart;
            if (loc >= 0 && loc < nk) {
                loadq(psrc + ((size_t)hb*NPP + p1)*KDD, qp1);
                float w = ex2(dotp(qp1, KsU[loc*4+0], KsU[loc*4+1], KsU[loc*4+2], KsU[loc*4+3]));
                accum(w, acc1, l1, VsU[loc*4+0], VsU[loc*4+1], VsU[loc*4+2], VsU[loc*4+3]);
            }
        }
    }

    if (v0) {
        float4* o = (float4*)(g_pacc[z] + ((size_t)hb*GG + n0)*KDD);
#pragma unroll
        for (int t = 0; t < 4; t++) {
            float2 a0 = up2(acc0[2*t]);
            float2 a1 = up2(acc0[2*t+1]);
            o[t] = make_float4(a0.x, a0.y, a1.x, a1.y);
        }
        g_pl[z][(size_t)hb*GG + n0] = l0;
    }
    if (v1) {
        float4* o = (float4*)(g_pacc[z] + ((size_t)hb*GG + n1)*KDD);
#pragma unroll
        for (int t = 0; t < 4; t++) {
            float2 a0 = up2(acc1[2*t]);
            float2 a1 = up2(acc1[2*t+1]);
            o[t] = make_float4(a0.x, a0.y, a1.x, a1.y);
        }
        g_pl[z][(size_t)hb*GG + n1] = l1;
    }
}

// ---------------------------------------------------------------------------
// Kernel 3a: combine 4 partials + normalize -> g_headsT [tok][hk].
// Massively parallel; coalesced float4 writes; partial reads 64B-chunked.
// ---------------------------------------------------------------------------
__global__ void __launch_bounds__(256) combine_kernel() {
    const int i = blockIdx.x * 256 + threadIdx.x;     // over NTOK*32 float4s
    if (i >= NTOK*32) return;
    const int t = i >> 5, sub = i & 31;               // sub = h*4 + k4
    const int h = sub >> 2, k4 = sub & 3;
    const size_t lidx = (size_t)h*NTOK + t;
    float l = (g_pl[0][lidx] + g_pl[1][lidx]) + (g_pl[2][lidx] + g_pl[3][lidx]);
    const float s = 1.0f / l;
    const size_t idx4 = lidx*4 + k4;
    float4 a = ((const float4*)g_pacc[0])[idx4];
    float4 b = ((const float4*)g_pacc[1])[idx4];
    float4 c = ((const float4*)g_pacc[2])[idx4];
    float4 d = ((const float4*)g_pacc[3])[idx4];
    float4 v = make_float4(((a.x+b.x)+(c.x+d.x))*s, ((a.y+b.y)+(c.y+d.y))*s,
                           ((a.z+b.z)+(c.z+d.z))*s, ((a.w+b.w)+(c.w+d.w))*s);
    ((float4*)g_headsT)[(size_t)t*32 + sub] = v;
}

// ---------------------------------------------------------------------------
// Kernel 3b: output GEMM. out[t,e] = sum_hk headsT[t,hk]*Wout[hk,e].
// grid (251 token-tiles of 32, 2 E-halves), block 256, smem ~50KB -> 4/SM.
// Thread: 1 token x 8 packed e-cols.
// ---------------------------------------------------------------------------
__global__ void __launch_bounds__(256, 4) out_kernel(const float* __restrict__ Wout,
                                                     float* __restrict__ out) {
    extern __shared__ float sm[];
    float* hs = sm;                  // 32 * 132 (padded rows)
    float* ws = sm + 32*132;         // 128 * 64 (E half)

    const int tid = threadIdx.x;
    const int t0  = blockIdx.x * 32;
    const int ech = blockIdx.y;

    // ws: cols [ech*64, +64), float4 copy
    {
        const float4* W4 = (const float4*)Wout;
        float4* ws4 = (float4*)ws;
        for (int i = tid; i < 128*16; i += 256) {
            int hk = i >> 4, c4 = i & 15;
            ws4[i] = W4[hk*32 + ech*16 + c4];
        }
    }
    // hs: straight contiguous rows from g_headsT
    {
        float4* hs4 = (float4*)hs;
        for (int i = tid; i < 32*32; i += 256) {
            int t = i >> 5, c4 = i & 31;
            float4 v = make_float4(0.f, 0.f, 0.f, 0.f);
            if (t0 + t < NTOK) v = ((const float4*)g_headsT)[(size_t)(t0 + t)*32 + c4];
            hs4[t*33 + c4] = v;
        }
    }
    __syncthreads();

    const int eg = tid & 7;          // cols eg*8 .. +7 within the 64-col half
    const int tk = tid >> 3;         // token 0..31
    const ulonglong2* wsU = (const ulonglong2*)ws;   // 16 per hk-row
    const float* hrow = hs + tk*132;

    ull acc[4];
#pragma unroll
    for (int c = 0; c < 4; c++) acc[c] = 0ull;

#pragma unroll 8
    for (int hk = 0; hk < 128; hk++) {
        ulonglong2 wa = wsU[hk*16 + eg*2];
        ulonglong2 wb = wsU[hk*16 + eg*2 + 1];
        float hv = hrow[hk];
        ull hb = pk2(hv, hv);
        fma2(acc[0], hb, wa.x);
        fma2(acc[1], hb, wa.y);
        fma2(acc[2], hb, wb.x);
        fma2(acc[3], hb, wb.y);
    }

    const int tt = t0 + tk;
    if (tt < NTOK) {
        float2 a0 = up2(acc[0]), a1 = up2(acc[1]);
        float2 a2 = up2(acc[2]), a3 = up2(acc[3]);
        float* o = out + (size_t)tt*EE + ech*64 + eg*8;
        *(float4*)(o)     = make_float4(a0.x, a0.y, a1.x, a1.y);
        *(float4*)(o + 4) = make_float4(a2.x, a2.y, a3.x, a3.y);
    }
}

// ---------------------------------------------------------------------------
extern "C" void kernel_launch(void* const* d_in, const int* in_sizes, int n_in,
                              void* d_out, int out_size) {
    const float* q = (const float*)d_in[0];
    WArgs wa;
    for (int i = 0; i < 9; i++) wa.w[i] = (const float*)d_in[1 + i];
    const float* Wout = (const float*)d_in[10];
    float* out = (float*)d_out;

    const int projSmem = (128*128 + 128*64) * sizeof(float);     // 98304 B
    const int attnSmem = 126*KDD*2*sizeof(float);                // 16128 B
    const int outSmem  = (32*132 + 128*64) * sizeof(float);      // 49664 B
    cudaFuncSetAttribute(proj_kernel, cudaFuncAttributeMaxDynamicSharedMemorySize, projSmem);
    cudaFuncSetAttribute(attn_kernel, cudaFuncAttributeMaxDynamicSharedMemorySize, attnSmem);
    cudaFuncSetAttribute(out_kernel,  cudaFuncAttributeMaxDynamicSharedMemorySize, outSmem);

    transpose_kernel<<<dim3((NTOK + 31)/32, 4), dim3(32, 8)>>>(q);
    proj_kernel<<<dim3(381, 2), 256, projSmem>>>(wa);
    attn_kernel<<<dim3(HH*BB, 2, 4), 128, attnSmem>>>();
    combine_kernel<<<(NTOK*32 + 255)/256, 256>>>();
    out_kernel<<<dim3((NTOK + 31)/32, 2), 256, outSmem>>>(Wout, out);
}

// round 15
// speedup vs baseline: 1.1026x; 1.1026x over previous
#include <cuda_runtime.h>

// ---------------------------------------------------------------------------
// Problem constants
// ---------------------------------------------------------------------------
#define HH   8
#define DD   128
#define KDD  16
#define EE   128
#define BB   16
#define GG   501
#define NPP  250
#define NTOK (BB*GG)      // 8016
#define NHALF (BB*NPP)    // 4000
#define SCALE2 0.3606737602222409f   // (1/sqrt(16)) * log2(e)

typedef unsigned long long ull;

// ---------------------------------------------------------------------------
// Scratch
// ---------------------------------------------------------------------------
__device__ float g_qT[DD*NTOK];            // transposed input: [d][token]
__device__ float g_Q[HH*NTOK*KDD];
__device__ float g_K[HH*NTOK*KDD];
__device__ float g_V[HH*NTOK*KDD];
// [0]=W1(pick single) [1]=W2(pick vs K_pick) [2]=W3(pick vs K_del)
// [3]=W4(del single)  [4]=W5(del vs K_del)   [5]=W6(del vs K_pick)
__device__ float g_EQ[6][HH*NHALF*KDD];
__device__ float g_pacc[4][HH*NTOK*KDD];   // partial sum(w*V) per key-quarter
__device__ float g_pl[4][HH*NTOK];         // partial sum(w)   per key-quarter

struct WArgs { const float* w[9]; };

// ---------------------------------------------------------------------------
// Packed fp32x2 helpers
// ---------------------------------------------------------------------------
__device__ __forceinline__ ull mul2(ull a, ull b) {
    ull r; asm("mul.rn.f32x2 %0,%1,%2;" : "=l"(r) : "l"(a), "l"(b)); return r;
}
__device__ __forceinline__ void fma2(ull& d, ull a, ull b) {
    asm("fma.rn.f32x2 %0,%1,%2,%0;" : "+l"(d) : "l"(a), "l"(b));
}
__device__ __forceinline__ ull add2(ull a, ull b) {
    ull r; asm("add.rn.f32x2 %0,%1,%2;" : "=l"(r) : "l"(a), "l"(b)); return r;
}
__device__ __forceinline__ ull pk2(float lo, float hi) {
    ull r; asm("mov.b64 %0,{%1,%2};" : "=l"(r) : "f"(lo), "f"(hi)); return r;
}
__device__ __forceinline__ float2 up2(ull a) {
    float lo, hi; asm("mov.b64 {%0,%1},%2;" : "=f"(lo), "=f"(hi) : "l"(a));
    return make_float2(lo, hi);
}
__device__ __forceinline__ float ex2(float x) {
    float r; asm("ex2.approx.f32 %0, %1;" : "=f"(r) : "f"(x)); return r;
}

// ---------------------------------------------------------------------------
// Kernel 0: transpose q [token][d] -> g_qT [d][token]. 32x32 tiles.
// ---------------------------------------------------------------------------
__global__ void transpose_kernel(const float* __restrict__ q) {
    __shared__ float s[32][33];
    const int t0 = blockIdx.x * 32;
    const int d0 = blockIdx.y * 32;
    const int x = threadIdx.x, y = threadIdx.y;   // block (32,8)
#pragma unroll
    for (int j = 0; j < 32; j += 8) {
        int t = t0 + y + j;
        s[y+j][x] = (t < NTOK) ? q[(size_t)t*DD + d0 + x] : 0.f;
    }
    __syncthreads();
#pragma unroll
    for (int j = 0; j < 32; j += 8) {
        int t = t0 + x;
        if (t < NTOK) g_qT[(size_t)(d0 + y + j)*NTOK + t] = s[x][y+j];
    }
}

// ---------------------------------------------------------------------------
// Kernel 1: projections as folded GEMMs, d-major q tile.
// Tile 128 rows x 64 cols, 256 threads, thread = 8 rows (4 pairs) x 4 cols.
// ---------------------------------------------------------------------------
__global__ void __launch_bounds__(256, 2) proj_kernel(WArgs a) {
    extern __shared__ float sm[];
    float* qsT = sm;              // 128 d x 128 rows
    float* ws  = sm + 128*128;    // 128 d x 64 cols

    int bx = blockIdx.x;
    const int ch = blockIdx.y;    // column half (0/1)
    int job, tile;
    if (bx < 189) { job = bx / 63; tile = bx % 63; }
    else          { bx -= 189; job = 3 + bx / 32; tile = bx % 32; }

    const bool full = (job < 3);
    const int nrows = full ? NTOK : NHALF;
    const int r0 = tile * 128;
    const int tid = threadIdx.x;

    {
        const float4* W4 = (const float4*)a.w[job];
        float4* ws4 = (float4*)ws;
        for (int i = tid; i < DD*16; i += 256) {
            int d = i >> 4, c4 = i & 15;
            int gc4 = ch*16 + c4;
            ws4[i] = W4[(gc4 >> 2)*(DD*4) + d*4 + (gc4 & 3)];
        }
    }

    if (full) {
        float4* q4 = (float4*)qsT;
        for (int i = tid; i < 128*32; i += 256) {
            int d = i >> 5, r4 = i & 31;
            int t = r0 + r4*4;
            float4 v = make_float4(0.f, 0.f, 0.f, 0.f);
            if (t < NTOK) v = *(const float4*)(g_qT + (size_t)d*NTOK + t);
            q4[d*32 + r4] = v;
        }
    } else {
        const int off = (job < 6) ? 1 : (NPP + 1);
        for (int i = tid; i < 128*128; i += 256) {
            int d = i >> 7, r = i & 127;
            int rt = r0 + r;
            float v = 0.f;
            if (rt < NHALF) {
                int b = rt / NPP, p = rt % NPP;
                v = g_qT[(size_t)d*NTOK + b*GG + off + p];
            }
            qsT[d*128 + r] = v;
        }
    }
    __syncthreads();

    const int cg = tid & 15;
    const int rg = tid >> 4;

    ull acc[4][4];
#pragma unroll
    for (int p = 0; p < 4; p++)
#pragma unroll
        for (int c = 0; c < 4; c++) acc[p][c] = 0ull;

#pragma unroll 4
    for (int d = 0; d < DD; d++) {
        const float* qb = qsT + d*128 + rg*8;
        ulonglong2 qa = *(const ulonglong2*)(qb);
        ulonglong2 qc = *(const ulonglong2*)(qb + 4);
        float4 w = *(const float4*)(ws + d*64 + cg*4);
        ull w0 = pk2(w.x, w.x), w1 = pk2(w.y, w.y);
        ull w2 = pk2(w.z, w.z), w3 = pk2(w.w, w.w);
        fma2(acc[0][0], qa.x, w0); fma2(acc[0][1], qa.x, w1);
        fma2(acc[0][2], qa.x, w2); fma2(acc[0][3], qa.x, w3);
        fma2(acc[1][0], qa.y, w0); fma2(acc[1][1], qa.y, w1);
        fma2(acc[1][2], qa.y, w2); fma2(acc[1][3], qa.y, w3);
        fma2(acc[2][0], qc.x, w0); fma2(acc[2][1], qc.x, w1);
        fma2(acc[2][2], qc.x, w2); fma2(acc[2][3], qc.x, w3);
        fma2(acc[3][0], qc.y, w0); fma2(acc[3][1], qc.y, w1);
        fma2(acc[3][2], qc.y, w2); fma2(acc[3][3], qc.y, w3);
    }

    float* outp;
    if      (job == 0) outp = g_Q;
    else if (job == 1) outp = g_K;
    else if (job == 2) outp = g_V;
    else               outp = g_EQ[job-3];

    const int gcol0 = ch*64 + cg*4;
    const int h  = gcol0 >> 4;
    const int k0 = gcol0 & 15;
#pragma unroll
    for (int p = 0; p < 4; p++) {
        float2 c0 = up2(acc[p][0]), c1 = up2(acc[p][1]);
        float2 c2 = up2(acc[p][2]), c3 = up2(acc[p][3]);
        int rlo = r0 + rg*8 + 2*p;
        if (rlo < nrows) {
            float* o = outp + ((size_t)h*nrows + rlo)*KDD + k0;
            *(float4*)o = make_float4(c0.x, c1.x, c2.x, c3.x);
        }
        if (rlo + 1 < nrows) {
            float* o = outp + ((size_t)h*nrows + rlo + 1)*KDD + k0;
            *(float4*)o = make_float4(c0.y, c1.y, c2.y, c3.y);
        }
    }
}

// ---------------------------------------------------------------------------
// Attention helpers. K/V row = 16 floats = 4 ulonglong2.
// ---------------------------------------------------------------------------
__device__ __forceinline__ float dotp(const ull* qp,
        ulonglong2 ka, ulonglong2 kb, ulonglong2 kc, ulonglong2 kd) {
    ull p0 = mul2(qp[0], ka.x);
    ull p1 = mul2(qp[1], ka.y);
    fma2(p0, qp[2], kb.x); fma2(p1, qp[3], kb.y);
    fma2(p0, qp[4], kc.x); fma2(p1, qp[5], kc.y);
    fma2(p0, qp[6], kd.x); fma2(p1, qp[7], kd.y);
    float2 s = up2(add2(p0, p1));
    return s.x + s.y;
}

__device__ __forceinline__ void accum(float w, ull* acc, float& l,
        ulonglong2 va, ulonglong2 vb, ulonglong2 vc, ulonglong2 vd) {
    l += w;
    ull wp = pk2(w, w);
    fma2(acc[0], wp, va.x); fma2(acc[1], wp, va.y);
    fma2(acc[2], wp, vb.x); fma2(acc[3], wp, vb.y);
    fma2(acc[4], wp, vc.x); fma2(acc[5], wp, vc.y);
    fma2(acc[6], wp, vd.x); fma2(acc[7], wp, vd.y);
}

__device__ __forceinline__ void attn_key2(const ulonglong2* KsU, const ulonglong2* VsU,
        int j,
        const ull* qp0, bool a0, float& l0, ull* acc0,
        const ull* qp1, bool a1, float& l1, ull* acc1) {
    ulonglong2 ka = KsU[j*4+0], kb = KsU[j*4+1], kc = KsU[j*4+2], kd = KsU[j*4+3];
    float s0 = dotp(qp0, ka, kb, kc, kd);
    float s1 = dotp(qp1, ka, kb, kc, kd);
    float w0 = a0 ? ex2(s0) : 0.f;
    float w1 = a1 ? ex2(s1) : 0.f;
    ulonglong2 va = VsU[j*4+0], vb = VsU[j*4+1], vc = VsU[j*4+2], vd = VsU[j*4+3];
    accum(w0, acc0, l0, va, vb, vc, vd);
    accum(w1, acc1, l1, va, vb, vc, vd);
}

__device__ __forceinline__ void loadq(const float* src, ull* qp) {
    const float4* s4 = (const float4*)src;
#pragma unroll
    for (int t = 0; t < 4; t++) {
        float4 v = s4[t];
        qp[2*t]   = pk2(v.x*SCALE2, v.y*SCALE2);
        qp[2*t+1] = pk2(v.z*SCALE2, v.w*SCALE2);
    }
}

// ---------------------------------------------------------------------------
// Kernel 2: attention split over key QUARTERS.
// grid (HB=128, 2 qchunks, 4 key-quarters), block 128, 2 queries/thread.
// ---------------------------------------------------------------------------
__global__ void __launch_bounds__(128, 4) attn_kernel() {
    extern __shared__ float sm[];
    const ulonglong2* KsU = (const ulonglong2*)sm;        // 126 rows * 4
    const ulonglong2* VsU = KsU + 126*4;

    const int hb  = blockIdx.x;
    const int tid = threadIdx.x;
    const int z   = blockIdx.z;
    const int kstart = (z==0) ? 0 : (z==1) ? 126 : (z==2) ? 251 : 376;
    const int nk     = (z==0) ? 126 : 125;

    {
        const float4* K4 = (const float4*)(g_K + ((size_t)hb*GG + kstart)*KDD);
        const float4* V4 = (const float4*)(g_V + ((size_t)hb*GG + kstart)*KDD);
        float4* Ks4 = (float4*)sm;
        float4* Vs4 = Ks4 + 126*4;
        for (int i = tid; i < nk*4; i += 128) {
            Ks4[i] = K4[i];
            Vs4[i] = V4[i];
        }
    }
    __syncthreads();

    const int base = blockIdx.y * 256;
    const int n0 = base + tid;
    const int n1 = base + 128 + tid;
    const bool v0 = (n0 < GG);
    const bool v1 = (n1 < GG);
    const int nn0 = v0 ? n0 : 0;
    const int nn1 = v1 ? n1 : 0;

    ull qp0[8], qp1[8], acc0[8], acc1[8];
    float l0 = 0.f, l1 = 0.f;
#pragma unroll
    for (int k = 0; k < 8; k++) { acc0[k] = 0ull; acc1[k] = 0ull; }
    loadq(g_Q + ((size_t)hb*GG + nn0)*KDD, qp0);
    loadq(g_Q + ((size_t)hb*GG + nn1)*KDD, qp1);

    for (int j = 0; j < nk; j++)
        attn_key2(KsU, VsU, j, qp0, true, l0, acc0, qp1, true, l1, acc1);

    const bool pk0 = (n0 >= 1) && (n0 <= NPP);
    const bool dl0 = (n0 >= NPP+1) && (n0 < GG);
    const bool ex0 = pk0 || dl0;
    const int  p0  = pk0 ? (n0-1) : (n0-NPP-1);
    const bool pk1 = (n1 >= 1) && (n1 <= NPP);
    const bool dl1 = (n1 >= NPP+1) && (n1 < GG);
    const bool ex1 = pk1 || dl1;
    const int  p1  = pk1 ? (n1-1) : (n1-NPP-1);

    {
        const float* e0src = (z < 2) ? (pk0 ? g_EQ[1] : g_EQ[5]) : (pk0 ? g_EQ[2] : g_EQ[4]);
        const float* e1src = (z < 2) ? (pk1 ? g_EQ[1] : g_EQ[5]) : (pk1 ? g_EQ[2] : g_EQ[4]);
        if (ex0) loadq(e0src + ((size_t)hb*NPP + p0)*KDD, qp0);
        if (ex1) loadq(e1src + ((size_t)hb*NPP + p1)*KDD, qp1);
        const int st = (z == 0) ? 1 : 0;
        for (int j = st; j < st + 125; j++)
            attn_key2(KsU, VsU, j, qp0, ex0, l0, acc0, qp1, ex1, l1, acc1);
    }

    {
        const bool c0 = (z < 2) ? dl0 : pk0;
        const bool c1 = (z < 2) ? dl1 : pk1;
        const float* psrc = (z < 2) ? g_EQ[3] : g_EQ[0];
        if (c0) {
            int keyg = ((z < 2) ? 1 : 251) + p0;
            int loc = keyg - kstart;
            if (loc >= 0 && loc < nk) {
                loadq(psrc + ((size_t)hb*NPP + p0)*KDD, qp0);
                float w = ex2(dotp(qp0, KsU[loc*4+0], KsU[loc*4+1], KsU[loc*4+2], KsU[loc*4+3]));
                accum(w, acc0, l0, VsU[loc*4+0], VsU[loc*4+1], VsU[loc*4+2], VsU[loc*4+3]);
            }
        }
        if (c1) {
            int keyg = ((z < 2) ? 1 : 251) + p1;
            int loc = keyg - kstart;
            if (loc >= 0 && loc < nk) {
                loadq(psrc + ((size_t)hb*NPP + p1)*KDD, qp1);
                float w = ex2(dotp(qp1, KsU[loc*4+0], KsU[loc*4+1], KsU[loc*4+2], KsU[loc*4+3]));
                accum(w, acc1, l1, VsU[loc*4+0], VsU[loc*4+1], VsU[loc*4+2], VsU[loc*4+3]);
            }
        }
    }

    if (v0) {
        float4* o = (float4*)(g_pacc[z] + ((size_t)hb*GG + n0)*KDD);
#pragma unroll
        for (int t = 0; t < 4; t++) {
            float2 a0 = up2(acc0[2*t]);
            float2 a1 = up2(acc0[2*t+1]);
            o[t] = make_float4(a0.x, a0.y, a1.x, a1.y);
        }
        g_pl[z][(size_t)hb*GG + n0] = l0;
    }
    if (v1) {
        float4* o = (float4*)(g_pacc[z] + ((size_t)hb*GG + n1)*KDD);
#pragma unroll
        for (int t = 0; t < 4; t++) {
            float2 a0 = up2(acc1[2*t]);
            float2 a1 = up2(acc1[2*t+1]);
            o[t] = make_float4(a0.x, a0.y, a1.x, a1.y);
        }
        g_pl[z][(size_t)hb*GG + n1] = l1;
    }
}

// ---------------------------------------------------------------------------
// Kernel 3: combine 4 partials + normalize + output projection (fused).
// 32-token tiles x full E -> grid 251, smem 83KB -> 2 blocks/SM.
// Combine decomposition: k4=tid&3, t=(tid>>2)&31, hbase=(tid>>7)*4, h=hbase+hh
// (hh=0..3) -> h in [0,7] always; fully coalesced per-h runs.
// Thread (GEMM phase): 2 tokens x 8 packed e-cols.
// ---------------------------------------------------------------------------
__global__ void __launch_bounds__(256, 2) out_kernel(const float* __restrict__ Wout,
                                                     float* __restrict__ out) {
    extern __shared__ float sm[];
    float* hs   = sm;                    // 32 * 132
    float* ws   = sm + 32*132;           // 128 * 128
    float* sinv = ws + 128*128;          // 32 * 8

    const int tid = threadIdx.x;
    const int t0  = blockIdx.x * 32;

    // ws: full Wout, straight float4 copy (L2-resident after first wave)
    {
        const float4* W4 = (const float4*)Wout;
        float4* ws4 = (float4*)ws;
        for (int i = tid; i < 128*32; i += 256) ws4[i] = W4[i];
    }
    // sinv: per (token, head) reciprocal of total l (t fastest -> coalesced)
    if (tid < 256) {
        int t = tid & 31, h = tid >> 5;
        int tt = t0 + t;
        float l = 1.f;
        if (tt < NTOK) {
            size_t idx = (size_t)h*NTOK + tt;
            l = (g_pl[0][idx] + g_pl[1][idx]) + (g_pl[2][idx] + g_pl[3][idx]);
        }
        sinv[t*8 + h] = 1.0f / l;
    }
    __syncthreads();

    // hs combine: per h, tids sweep contiguous (t,k4) float4 runs.
    {
        const int k4    = tid & 3;          // 0..3
        const int t     = (tid >> 2) & 31;  // 0..31
        const int hbase = (tid >> 7) * 4;   // 0 or 4
        const int tt    = t0 + t;
#pragma unroll
        for (int hh = 0; hh < 4; hh++) {
            const int h = hbase + hh;       // 0..7
            float4 v = make_float4(0.f, 0.f, 0.f, 0.f);
            if (tt < NTOK) {
                size_t idx4 = (((size_t)h*NTOK + tt) << 2) + k4;
                float4 a = ((const float4*)g_pacc[0])[idx4];
                float4 b = ((const float4*)g_pacc[1])[idx4];
                float4 c = ((const float4*)g_pacc[2])[idx4];
                float4 d = ((const float4*)g_pacc[3])[idx4];
                float s = sinv[t*8 + h];
                v = make_float4(((a.x+b.x)+(c.x+d.x))*s, ((a.y+b.y)+(c.y+d.y))*s,
                                ((a.z+b.z)+(c.z+d.z))*s, ((a.w+b.w)+(c.w+d.w))*s);
            }
            *(float4*)(hs + t*132 + h*16 + k4*4) = v;
        }
    }
    __syncthreads();

    const int eg = tid & 15;         // cols eg*8 .. +7
    const int tg = tid >> 4;         // 16 groups of 2 tokens
    const ulonglong2* wsU = (const ulonglong2*)ws;   // 32 per hk-row

    ull acc[2][4];
#pragma unroll
    for (int ti = 0; ti < 2; ti++)
#pragma unroll
        for (int c = 0; c < 4; c++) acc[ti][c] = 0ull;

#pragma unroll 4
    for (int hk = 0; hk < 128; hk++) {
        ulonglong2 wa = wsU[hk*32 + eg*2];
        ulonglong2 wb = wsU[hk*32 + eg*2 + 1];
        ull hb[2];
#pragma unroll
        for (int ti = 0; ti < 2; ti++) {
            float hv = hs[(tg*2 + ti)*132 + hk];
            hb[ti] = pk2(hv, hv);
        }
#pragma unroll
        for (int ti = 0; ti < 2; ti++) {
            fma2(acc[ti][0], hb[ti], wa.x);
            fma2(acc[ti][1], hb[ti], wa.y);
            fma2(acc[ti][2], hb[ti], wb.x);
            fma2(acc[ti][3], hb[ti], wb.y);
        }
    }

#pragma unroll
    for (int ti = 0; ti < 2; ti++) {
        int tt = t0 + tg*2 + ti;
        if (tt < NTOK) {
            float2 a0 = up2(acc[ti][0]), a1 = up2(acc[ti][1]);
            float2 a2 = up2(acc[ti][2]), a3 = up2(acc[ti][3]);
            float* o = out + (size_t)tt*EE + eg*8;
            *(float4*)(o)     = make_float4(a0.x, a0.y, a1.x, a1.y);
            *(float4*)(o + 4) = make_float4(a2.x, a2.y, a3.x, a3.y);
        }
    }
}

// ---------------------------------------------------------------------------
extern "C" void kernel_launch(void* const* d_in, const int* in_sizes, int n_in,
                              void* d_out, int out_size) {
    const float* q = (const float*)d_in[0];
    WArgs wa;
    for (int i = 0; i < 9; i++) wa.w[i] = (const float*)d_in[1 + i];
    const float* Wout = (const float*)d_in[10];
    float* out = (float*)d_out;

    const int projSmem = (128*128 + 128*64) * sizeof(float);     // 98304 B
    const int attnSmem = 126*KDD*2*sizeof(float);                // 16128 B
    const int outSmem  = (32*132 + 128*128 + 32*8) * sizeof(float); // 83456 B
    cudaFuncSetAttribute(proj_kernel, cudaFuncAttributeMaxDynamicSharedMemorySize, projSmem);
    cudaFuncSetAttribute(attn_kernel, cudaFuncAttributeMaxDynamicSharedMemorySize, attnSmem);
    cudaFuncSetAttribute(out_kernel,  cudaFuncAttributeMaxDynamicSharedMemorySize, outSmem);

    transpose_kernel<<<dim3((NTOK + 31)/32, 4), dim3(32, 8)>>>(q);
    proj_kernel<<<dim3(381, 2), 256, projSmem>>>(wa);
    attn_kernel<<<dim3(HH*BB, 2, 4), 128, attnSmem>>>();
    out_kernel<<<(NTOK + 31)/32, 256, outSmem>>>(Wout, out);
}

// round 16
// speedup vs baseline: 1.1070x; 1.0040x over previous
#include <cuda_runtime.h>

// ---------------------------------------------------------------------------
// Problem constants
// ---------------------------------------------------------------------------
#define HH   8
#define DD   128
#define KDD  16
#define EE   128
#define BB   16
#define GG   501
#define NPP  250
#define NTOK (BB*GG)      // 8016
#define NHALF (BB*NPP)    // 4000
#define SCALE2 0.3606737602222409f   // (1/sqrt(16)) * log2(e)

typedef unsigned long long ull;

// ---------------------------------------------------------------------------
// Scratch (g_qT padded +64: proj tail row-groups may over-read past last token)
// ---------------------------------------------------------------------------
__device__ float g_qT[DD*NTOK + 64];       // transposed input: [d][token]
__device__ float g_Q[HH*NTOK*KDD];
__device__ float g_K[HH*NTOK*KDD];
__device__ float g_V[HH*NTOK*KDD];
// [0]=W1(pick single) [1]=W2(pick vs K_pick) [2]=W3(pick vs K_del)
// [3]=W4(del single)  [4]=W5(del vs K_del)   [5]=W6(del vs K_pick)
__device__ float g_EQ[6][HH*NHALF*KDD];
__device__ float g_pacc[4][HH*NTOK*KDD];   // partial sum(w*V) per key-quarter
__device__ float g_pl[4][HH*NTOK];         // partial sum(w)   per key-quarter

struct WArgs { const float* w[9]; };

// ---------------------------------------------------------------------------
// Packed fp32x2 helpers
// ---------------------------------------------------------------------------
__device__ __forceinline__ ull mul2(ull a, ull b) {
    ull r; asm("mul.rn.f32x2 %0,%1,%2;" : "=l"(r) : "l"(a), "l"(b)); return r;
}
__device__ __forceinline__ void fma2(ull& d, ull a, ull b) {
    asm("fma.rn.f32x2 %0,%1,%2,%0;" : "+l"(d) : "l"(a), "l"(b));
}
__device__ __forceinline__ ull add2(ull a, ull b) {
    ull r; asm("add.rn.f32x2 %0,%1,%2;" : "=l"(r) : "l"(a), "l"(b)); return r;
}
__device__ __forceinline__ ull pk2(float lo, float hi) {
    ull r; asm("mov.b64 %0,{%1,%2};" : "=l"(r) : "f"(lo), "f"(hi)); return r;
}
__device__ __forceinline__ float2 up2(ull a) {
    float lo, hi; asm("mov.b64 {%0,%1},%2;" : "=f"(lo), "=f"(hi) : "l"(a));
    return make_float2(lo, hi);
}
__device__ __forceinline__ float ex2(float x) {
    float r; asm("ex2.approx.f32 %0, %1;" : "=f"(r) : "f"(x)); return r;
}

// ---------------------------------------------------------------------------
// Kernel 0: transpose q [token][d] -> g_qT [d][token]. 32x32 tiles.
// ---------------------------------------------------------------------------
__global__ void transpose_kernel(const float* __restrict__ q) {
    __shared__ float s[32][33];
    const int t0 = blockIdx.x * 32;
    const int d0 = blockIdx.y * 32;
    const int x = threadIdx.x, y = threadIdx.y;   // block (32,8)
#pragma unroll
    for (int j = 0; j < 32; j += 8) {
        int t = t0 + y + j;
        s[y+j][x] = (t < NTOK) ? q[(size_t)t*DD + d0 + x] : 0.f;
    }
    __syncthreads();
#pragma unroll
    for (int j = 0; j < 32; j += 8) {
        int t = t0 + x;
        if (t < NTOK) g_qT[(size_t)(d0 + y + j)*NTOK + t] = s[x][y+j];
    }
}

// ---------------------------------------------------------------------------
// Kernel 1: projections, q read DIRECT from g_qT (no q smem).
// smem = weight tile only (32KB). Tile 128 rows x 64 cols, 256 threads,
// thread = 8 rows (4 packed pairs) x 4 cols.
// Full jobs (0-2): rows = contiguous tokens, aligned -> LDG.128 row-pairs.
// Half jobs (3-8): tiled per (batch, part) so rows = contiguous tokens
// (possibly odd start) -> scalar loads + pk2. All q loads are warp-broadcast.
// grid (381, 2 col-halves): full 63 tiles/job, half 32 tiles/job.
// ---------------------------------------------------------------------------
__device__ __forceinline__ void pj_step(ull q0, ull q1, ull q2, ull q3,
                                        float4 w, ull acc[4][4]) {
    ull w0 = pk2(w.x, w.x), w1 = pk2(w.y, w.y);
    ull w2 = pk2(w.z, w.z), w3 = pk2(w.w, w.w);
    fma2(acc[0][0], q0, w0); fma2(acc[0][1], q0, w1);
    fma2(acc[0][2], q0, w2); fma2(acc[0][3], q0, w3);
    fma2(acc[1][0], q1, w0); fma2(acc[1][1], q1, w1);
    fma2(acc[1][2], q1, w2); fma2(acc[1][3], q1, w3);
    fma2(acc[2][0], q2, w0); fma2(acc[2][1], q2, w1);
    fma2(acc[2][2], q2, w2); fma2(acc[2][3], q2, w3);
    fma2(acc[3][0], q3, w0); fma2(acc[3][1], q3, w1);
    fma2(acc[3][2], q3, w2); fma2(acc[3][3], q3, w3);
}

__global__ void __launch_bounds__(256, 3) proj_kernel(WArgs a) {
    __shared__ float ws[DD*64];   // 32KB

    int bx = blockIdx.x;
    const int ch = blockIdx.y;    // column half (0/1)
    int job, tile;
    if (bx < 189) { job = bx / 63; tile = bx % 63; }
    else          { bx -= 189; job = 3 + bx / 32; tile = bx % 32; }

    const bool full = (job < 3);
    const int tid = threadIdx.x;

    // ---- weight tile (float4): ws[d*64+col] ----
    {
        const float4* W4 = (const float4*)a.w[job];
        float4* ws4 = (float4*)ws;
        for (int i = tid; i < DD*16; i += 256) {
            int d = i >> 4, c4 = i & 15;
            int gc4 = ch*16 + c4;
            ws4[i] = W4[(gc4 >> 2)*(DD*4) + d*4 + (gc4 & 3)];
        }
    }
    __syncthreads();

    // ---- tile -> token range + output row base ----
    int tok0, nr, orow0;
    if (full) {
        tok0 = tile * 128;
        nr = NTOK - tok0; if (nr > 128) nr = 128;
        orow0 = tok0;
    } else {
        int b = tile >> 1, part = tile & 1;
        int off = (job < 6) ? 1 : (NPP + 1);
        tok0 = b*GG + off + part*128;
        nr = part ? (NPP - 128) : 128;      // 122 or 128
        orow0 = b*NPP + part*128;
    }

    const int cg = tid & 15;      // cols cg*4 .. +3 (within 64-col half)
    const int rg = tid >> 4;      // rows rg*8 .. +7 (4 packed pairs)

    ull acc[4][4];
#pragma unroll
    for (int p = 0; p < 4; p++)
#pragma unroll
        for (int c = 0; c < 4; c++) acc[p][c] = 0ull;

    const float* qbase = g_qT + tok0 + rg*8;

    if (full) {
#pragma unroll 4
        for (int d = 0; d < DD; d++) {
            const float* qb = qbase + (size_t)d*NTOK;
            ulonglong2 qa = *(const ulonglong2*)qb;        // pairs (r0,r1),(r2,r3)
            ulonglong2 qc = *(const ulonglong2*)(qb + 4);  // pairs (r4,r5),(r6,r7)
            float4 w = *(const float4*)(ws + d*64 + cg*4);
            pj_step(qa.x, qa.y, qc.x, qc.y, w, acc);
        }
    } else {
#pragma unroll 4
        for (int d = 0; d < DD; d++) {
            const float* qb = qbase + (size_t)d*NTOK;
            ull q0 = pk2(qb[0], qb[1]);
            ull q1 = pk2(qb[2], qb[3]);
            ull q2 = pk2(qb[4], qb[5]);
            ull q3 = pk2(qb[6], qb[7]);
            float4 w = *(const float4*)(ws + d*64 + cg*4);
            pj_step(q0, q1, q2, q3, w, acc);
        }
    }

    float* outp;
    int nrows;
    if      (job == 0) { outp = g_Q; nrows = NTOK; }
    else if (job == 1) { outp = g_K; nrows = NTOK; }
    else if (job == 2) { outp = g_V; nrows = NTOK; }
    else               { outp = g_EQ[job-3]; nrows = NHALF; }

    const int gcol0 = ch*64 + cg*4;
    const int h  = gcol0 >> 4;
    const int k0 = gcol0 & 15;
#pragma unroll
    for (int p = 0; p < 4; p++) {
        float2 c0 = up2(acc[p][0]), c1 = up2(acc[p][1]);
        float2 c2 = up2(acc[p][2]), c3 = up2(acc[p][3]);
        int rr = rg*8 + 2*p;
        if (rr < nr) {
            float* o = outp + ((size_t)h*nrows + orow0 + rr)*KDD + k0;
            *(float4*)o = make_float4(c0.x, c1.x, c2.x, c3.x);
        }
        if (rr + 1 < nr) {
            float* o = outp + ((size_t)h*nrows + orow0 + rr + 1)*KDD + k0;
            *(float4*)o = make_float4(c0.y, c1.y, c2.y, c3.y);
        }
    }
}

// ---------------------------------------------------------------------------
// Attention helpers. K/V row = 16 floats = 4 ulonglong2.
// ---------------------------------------------------------------------------
__device__ __forceinline__ float dotp(const ull* qp,
        ulonglong2 ka, ulonglong2 kb, ulonglong2 kc, ulonglong2 kd) {
    ull p0 = mul2(qp[0], ka.x);
    ull p1 = mul2(qp[1], ka.y);
    fma2(p0, qp[2], kb.x); fma2(p1, qp[3], kb.y);
    fma2(p0, qp[4], kc.x); fma2(p1, qp[5], kc.y);
    fma2(p0, qp[6], kd.x); fma2(p1, qp[7], kd.y);
    float2 s = up2(add2(p0, p1));
    return s.x + s.y;
}

__device__ __forceinline__ void accum(float w, ull* acc, float& l,
        ulonglong2 va, ulonglong2 vb, ulonglong2 vc, ulonglong2 vd) {
    l += w;
    ull wp = pk2(w, w);
    fma2(acc[0], wp, va.x); fma2(acc[1], wp, va.y);
    fma2(acc[2], wp, vb.x); fma2(acc[3], wp, vb.y);
    fma2(acc[4], wp, vc.x); fma2(acc[5], wp, vc.y);
    fma2(acc[6], wp, vd.x); fma2(acc[7], wp, vd.y);
}

__device__ __forceinline__ void attn_key2(const ulonglong2* KsU, const ulonglong2* VsU,
        int j,
        const ull* qp0, bool a0, float& l0, ull* acc0,
        const ull* qp1, bool a1, float& l1, ull* acc1) {
    ulonglong2 ka = KsU[j*4+0], kb = KsU[j*4+1], kc = KsU[j*4+2], kd = KsU[j*4+3];
    float s0 = dotp(qp0, ka, kb, kc, kd);
    float s1 = dotp(qp1, ka, kb, kc, kd);
    float w0 = a0 ? ex2(s0) : 0.f;
    float w1 = a1 ? ex2(s1) : 0.f;
    ulonglong2 va = VsU[j*4+0], vb = VsU[j*4+1], vc = VsU[j*4+2], vd = VsU[j*4+3];
    accum(w0, acc0, l0, va, vb, vc, vd);
    accum(w1, acc1, l1, va, vb, vc, vd);
}

__device__ __forceinline__ void loadq(const float* src, ull* qp) {
    const float4* s4 = (const float4*)src;
#pragma unroll
    for (int t = 0; t < 4; t++) {
        float4 v = s4[t];
        qp[2*t]   = pk2(v.x*SCALE2, v.y*SCALE2);
        qp[2*t+1] = pk2(v.z*SCALE2, v.w*SCALE2);
    }
}

// ---------------------------------------------------------------------------
// Kernel 2: attention split over key QUARTERS.
// grid (HB=128, 2 qchunks, 4 key-quarters), block 128, 2 queries/thread.
// ---------------------------------------------------------------------------
__global__ void __launch_bounds__(128, 4) attn_kernel() {
    extern __shared__ float sm[];
    const ulonglong2* KsU = (const ulonglong2*)sm;        // 126 rows * 4
    const ulonglong2* VsU = KsU + 126*4;

    const int hb  = blockIdx.x;
    const int tid = threadIdx.x;
    const int z   = blockIdx.z;
    const int kstart = (z==0) ? 0 : (z==1) ? 126 : (z==2) ? 251 : 376;
    const int nk     = (z==0) ? 126 : 125;

    {
        const float4* K4 = (const float4*)(g_K + ((size_t)hb*GG + kstart)*KDD);
        const float4* V4 = (const float4*)(g_V + ((size_t)hb*GG + kstart)*KDD);
        float4* Ks4 = (float4*)sm;
        float4* Vs4 = Ks4 + 126*4;
        for (int i = tid; i < nk*4; i += 128) {
            Ks4[i] = K4[i];
            Vs4[i] = V4[i];
        }
    }
    __syncthreads();

    const int base = blockIdx.y * 256;
    const int n0 = base + tid;
    const int n1 = base + 128 + tid;
    const bool v0 = (n0 < GG);
    const bool v1 = (n1 < GG);
    const int nn0 = v0 ? n0 : 0;
    const int nn1 = v1 ? n1 : 0;

    ull qp0[8], qp1[8], acc0[8], acc1[8];
    float l0 = 0.f, l1 = 0.f;
#pragma unroll
    for (int k = 0; k < 8; k++) { acc0[k] = 0ull; acc1[k] = 0ull; }
    loadq(g_Q + ((size_t)hb*GG + nn0)*KDD, qp0);
    loadq(g_Q + ((size_t)hb*GG + nn1)*KDD, qp1);

    for (int j = 0; j < nk; j++)
        attn_key2(KsU, VsU, j, qp0, true, l0, acc0, qp1, true, l1, acc1);

    const bool pk0 = (n0 >= 1) && (n0 <= NPP);
    const bool dl0 = (n0 >= NPP+1) && (n0 < GG);
    const bool ex0 = pk0 || dl0;
    const int  p0  = pk0 ? (n0-1) : (n0-NPP-1);
    const bool pk1 = (n1 >= 1) && (n1 <= NPP);
    const bool dl1 = (n1 >= NPP+1) && (n1 < GG);
    const bool ex1 = pk1 || dl1;
    const int  p1  = pk1 ? (n1-1) : (n1-NPP-1);

    {
        const float* e0src = (z < 2) ? (pk0 ? g_EQ[1] : g_EQ[5]) : (pk0 ? g_EQ[2] : g_EQ[4]);
        const float* e1src = (z < 2) ? (pk1 ? g_EQ[1] : g_EQ[5]) : (pk1 ? g_EQ[2] : g_EQ[4]);
        if (ex0) loadq(e0src + ((size_t)hb*NPP + p0)*KDD, qp0);
        if (ex1) loadq(e1src + ((size_t)hb*NPP + p1)*KDD, qp1);
        const int st = (z == 0) ? 1 : 0;
        for (int j = st; j < st + 125; j++)
            attn_key2(KsU, VsU, j, qp0, ex0, l0, acc0, qp1, ex1, l1, acc1);
    }

    {
        const bool c0 = (z < 2) ? dl0 : pk0;
        const bool c1 = (z < 2) ? dl1 : pk1;
        const float* psrc = (z < 2) ? g_EQ[3] : g_EQ[0];
        if (c0) {
            int keyg = ((z < 2) ? 1 : 251) + p0;
            int loc = keyg - kstart;
            if (loc >= 0 && loc < nk) {
                loadq(psrc + ((size_t)hb*NPP + p0)*KDD, qp0);
                float w = ex2(dotp(qp0, KsU[loc*4+0], KsU[loc*4+1], KsU[loc*4+2], KsU[loc*4+3]));
                accum(w, acc0, l0, VsU[loc*4+0], VsU[loc*4+1], VsU[loc*4+2], VsU[loc*4+3]);
            }
        }
        if (c1) {
            int keyg = ((z < 2) ? 1 : 251) + p1;
            int loc = keyg - kstart;
            if (loc >= 0 && loc < nk) {
                loadq(psrc + ((size_t)hb*NPP + p1)*KDD, qp1);
                float w = ex2(dotp(qp1, KsU[loc*4+0], KsU[loc*4+1], KsU[loc*4+2], KsU[loc*4+3]));
                accum(w, acc1, l1, VsU[loc*4+0], VsU[loc*4+1], VsU[loc*4+2], VsU[loc*4+3]);
            }
        }
    }

    if (v0) {
        float4* o = (float4*)(g_pacc[z] + ((size_t)hb*GG + n0)*KDD);
#pragma unroll
        for (int t = 0; t < 4; t++) {
            float2 a0 = up2(acc0[2*t]);
            float2 a1 = up2(acc0[2*t+1]);
            o[t] = make_float4(a0.x, a0.y, a1.x, a1.y);
        }
        g_pl[z][(size_t)hb*GG + n0] = l0;
    }
    if (v1) {
        float4* o = (float4*)(g_pacc[z] + ((size_t)hb*GG + n1)*KDD);
#pragma unroll
        for (int t = 0; t < 4; t++) {
            float2 a0 = up2(acc1[2*t]);
            float2 a1 = up2(acc1[2*t+1]);
            o[t] = make_float4(a0.x, a0.y, a1.x, a1.y);
        }
        g_pl[z][(size_t)hb*GG + n1] = l1;
    }
}

// ---------------------------------------------------------------------------
// Kernel 3: combine 4 partials + normalize + output projection (R12 version —
// best measured, 27.7us). grid 126 (64-token tiles), block 256.
// ---------------------------------------------------------------------------
__global__ void __launch_bounds__(256, 2) out_kernel(const float* __restrict__ Wout,
                                                     float* __restrict__ out) {
    extern __shared__ float sm[];
    float* hs   = sm;                    // 64 * 132
    float* ws   = sm + 64*132;           // 128 * 128
    float* sinv = ws + 128*128;          // 64 * 8

    const int tid = threadIdx.x;
    const int t0  = blockIdx.x * 64;

    {
        const float4* W4 = (const float4*)Wout;
        float4* ws4 = (float4*)ws;
        for (int i = tid; i < 128*32; i += 256) ws4[i] = W4[i];
    }
    for (int i = tid; i < 64*8; i += 256) {
        int t = i & 63, h = i >> 6;
        int tt = t0 + t;
        float l = 1.f;
        if (tt < NTOK) {
            size_t idx = (size_t)h*NTOK + tt;
            l = (g_pl[0][idx] + g_pl[1][idx]) + (g_pl[2][idx] + g_pl[3][idx]);
        }
        sinv[t*8 + h] = 1.0f / l;
    }
    __syncthreads();

    {
        const int t  = tid >> 2;     // 0..63
        const int k4 = tid & 3;      // 0..3
        const int tt = t0 + t;
#pragma unroll
        for (int h = 0; h < 8; h++) {
            float4 v = make_float4(0.f, 0.f, 0.f, 0.f);
            if (tt < NTOK) {
                size_t idx4 = (((size_t)h*NTOK + tt) << 2) + k4;
                float4 a = ((const float4*)g_pacc[0])[idx4];
                float4 b = ((const float4*)g_pacc[1])[idx4];
                float4 c = ((const float4*)g_pacc[2])[idx4];
                float4 d = ((const float4*)g_pacc[3])[idx4];
                float s = sinv[t*8 + h];
                v = make_float4(((a.x+b.x)+(c.x+d.x))*s, ((a.y+b.y)+(c.y+d.y))*s,
                                ((a.z+b.z)+(c.z+d.z))*s, ((a.w+b.w)+(c.w+d.w))*s);
            }
            *(float4*)(hs + t*132 + h*16 + k4*4) = v;
        }
    }
    __syncthreads();

    const int eg = tid & 15;         // cols eg*8 .. +7
    const int tg = tid >> 4;         // 16 groups of 4 tokens
    const ulonglong2* wsU = (const ulonglong2*)ws;   // 32 per hk-row

    ull acc[4][4];
#pragma unroll
    for (int ti = 0; ti < 4; ti++)
#pragma unroll
        for (int c = 0; c < 4; c++) acc[ti][c] = 0ull;

#pragma unroll 4
    for (int hk = 0; hk < 128; hk++) {
        ulonglong2 wa = wsU[hk*32 + eg*2];
        ulonglong2 wb = wsU[hk*32 + eg*2 + 1];
        ull hb[4];
#pragma unroll
        for (int ti = 0; ti < 4; ti++) {
            float hv = hs[(tg*4 + ti)*132 + hk];
            hb[ti] = pk2(hv, hv);
        }
#pragma unroll
        for (int ti = 0; ti < 4; ti++) {
            fma2(acc[ti][0], hb[ti], wa.x);
            fma2(acc[ti][1], hb[ti], wa.y);
            fma2(acc[ti][2], hb[ti], wb.x);
            fma2(acc[ti][3], hb[ti], wb.y);
        }
    }

#pragma unroll
    for (int ti = 0; ti < 4; ti++) {
        int tt = t0 + tg*4 + ti;
        if (tt < NTOK) {
            float2 a0 = up2(acc[ti][0]), a1 = up2(acc[ti][1]);
            float2 a2 = up2(acc[ti][2]), a3 = up2(acc[ti][3]);
            float* o = out + (size_t)tt*EE + eg*8;
            *(float4*)(o)     = make_float4(a0.x, a0.y, a1.x, a1.y);
            *(float4*)(o + 4) = make_float4(a2.x, a2.y, a3.x, a3.y);
        }
    }
}

// ---------------------------------------------------------------------------
extern "C" void kernel_launch(void* const* d_in, const int* in_sizes, int n_in,
                              void* d_out, int out_size) {
    const float* q = (const float*)d_in[0];
    WArgs wa;
    for (int i = 0; i < 9; i++) wa.w[i] = (const float*)d_in[1 + i];
    const float* Wout = (const float*)d_in[10];
    float* out = (float*)d_out;

    const int attnSmem = 126*KDD*2*sizeof(float);                   // 16128 B
    const int outSmem  = (64*132 + 128*128 + 64*8) * sizeof(float); // 101376 B
    cudaFuncSetAttribute(attn_kernel, cudaFuncAttributeMaxDynamicSharedMemorySize, attnSmem);
    cudaFuncSetAttribute(out_kernel,  cudaFuncAttributeMaxDynamicSharedMemorySize, outSmem);

    transpose_kernel<<<dim3((NTOK + 31)/32, 4), dim3(32, 8)>>>(q);
    proj_kernel<<<dim3(381, 2), 256>>>(wa);
    attn_kernel<<<dim3(HH*BB, 2, 4), 128, attnSmem>>>();
    out_kernel<<<(NTOK + 63)/64, 256, outSmem>>>(Wout, out);
}

// round 17
// speedup vs baseline: 1.2864x; 1.1621x over previous
#include <cuda_runtime.h>

// ---------------------------------------------------------------------------
// Problem constants
// ---------------------------------------------------------------------------
#define HH   8
#define DD   128
#define KDD  16
#define EE   128
#define BB   16
#define GG   501
#define NPP  250
#define NTOK (BB*GG)      // 8016
#define NHALF (BB*NPP)    // 4000
#define SCALE2 0.3606737602222409f   // (1/sqrt(16)) * log2(e)

typedef unsigned long long ull;

// ---------------------------------------------------------------------------
// Scratch
// ---------------------------------------------------------------------------
__device__ float g_qT[DD*NTOK];            // transposed input: [d][token]
__device__ float g_Q[HH*NTOK*KDD];
__device__ float g_K[HH*NTOK*KDD];
__device__ float g_V[HH*NTOK*KDD];
// [0]=W1(pick single) [1]=W2(pick vs K_pick) [2]=W3(pick vs K_del)
// [3]=W4(del single)  [4]=W5(del vs K_del)   [5]=W6(del vs K_pick)
__device__ float g_EQ[6][HH*NHALF*KDD];
__device__ float g_pacc[2][HH*NTOK*KDD];   // partial sum(w*V) per key-half
__device__ float g_pl[2][HH*NTOK];         // partial sum(w)   per key-half

struct WArgs { const float* w[9]; };

// ---------------------------------------------------------------------------
// Packed fp32x2 helpers
// ---------------------------------------------------------------------------
__device__ __forceinline__ ull mul2(ull a, ull b) {
    ull r; asm("mul.rn.f32x2 %0,%1,%2;" : "=l"(r) : "l"(a), "l"(b)); return r;
}
__device__ __forceinline__ void fma2(ull& d, ull a, ull b) {
    asm("fma.rn.f32x2 %0,%1,%2,%0;" : "+l"(d) : "l"(a), "l"(b));
}
__device__ __forceinline__ ull add2(ull a, ull b) {
    ull r; asm("add.rn.f32x2 %0,%1,%2;" : "=l"(r) : "l"(a), "l"(b)); return r;
}
__device__ __forceinline__ ull pk2(float lo, float hi) {
    ull r; asm("mov.b64 %0,{%1,%2};" : "=l"(r) : "f"(lo), "f"(hi)); return r;
}
__device__ __forceinline__ float2 up2(ull a) {
    float lo, hi; asm("mov.b64 {%0,%1},%2;" : "=f"(lo), "=f"(hi) : "l"(a));
    return make_float2(lo, hi);
}
__device__ __forceinline__ float ex2(float x) {
    float r; asm("ex2.approx.f32 %0, %1;" : "=f"(r) : "f"(x)); return r;
}

// ---------------------------------------------------------------------------
// Kernel 0: transpose q [token][d] -> g_qT [d][token]. 32x32 tiles.
// ---------------------------------------------------------------------------
__global__ void transpose_kernel(const float* __restrict__ q) {
    __shared__ float s[32][33];
    const int t0 = blockIdx.x * 32;
    const int d0 = blockIdx.y * 32;
    const int x = threadIdx.x, y = threadIdx.y;   // block (32,8)
#pragma unroll
    for (int j = 0; j < 32; j += 8) {
        int t = t0 + y + j;
        s[y+j][x] = (t < NTOK) ? q[(size_t)t*DD + d0 + x] : 0.f;
    }
    __syncthreads();
#pragma unroll
    for (int j = 0; j < 32; j += 8) {
        int t = t0 + x;
        if (t < NTOK) g_qT[(size_t)(d0 + y + j)*NTOK + t] = s[x][y+j];
    }
}

// ---------------------------------------------------------------------------
// Kernel 1: projections as folded GEMMs, d-major q tile (R12 version — best
// measured). Tile 128 rows x 64 cols, 256 threads, 8 rows x 4 cols/thread.
// ---------------------------------------------------------------------------
__global__ void __launch_bounds__(256, 2) proj_kernel(WArgs a) {
    extern __shared__ float sm[];
    float* qsT = sm;              // 128 d x 128 rows
    float* ws  = sm + 128*128;    // 128 d x 64 cols

    int bx = blockIdx.x;
    const int ch = blockIdx.y;    // column half (0/1)
    int job, tile;
    if (bx < 189) { job = bx / 63; tile = bx % 63; }
    else          { bx -= 189; job = 3 + bx / 32; tile = bx % 32; }

    const bool full = (job < 3);
    const int nrows = full ? NTOK : NHALF;
    const int r0 = tile * 128;
    const int tid = threadIdx.x;

    {
        const float4* W4 = (const float4*)a.w[job];
        float4* ws4 = (float4*)ws;
        for (int i = tid; i < DD*16; i += 256) {
            int d = i >> 4, c4 = i & 15;
            int gc4 = ch*16 + c4;
            ws4[i] = W4[(gc4 >> 2)*(DD*4) + d*4 + (gc4 & 3)];
        }
    }

    if (full) {
        float4* q4 = (float4*)qsT;
        for (int i = tid; i < 128*32; i += 256) {
            int d = i >> 5, r4 = i & 31;
            int t = r0 + r4*4;
            float4 v = make_float4(0.f, 0.f, 0.f, 0.f);
            if (t < NTOK) v = *(const float4*)(g_qT + (size_t)d*NTOK + t);
            q4[d*32 + r4] = v;
        }
    } else {
        const int off = (job < 6) ? 1 : (NPP + 1);
        for (int i = tid; i < 128*128; i += 256) {
            int d = i >> 7, r = i & 127;
            int rt = r0 + r;
            float v = 0.f;
            if (rt < NHALF) {
                int b = rt / NPP, p = rt % NPP;
                v = g_qT[(size_t)d*NTOK + b*GG + off + p];
            }
            qsT[d*128 + r] = v;
        }
    }
    __syncthreads();

    const int cg = tid & 15;
    const int rg = tid >> 4;

    ull acc[4][4];
#pragma unroll
    for (int p = 0; p < 4; p++)
#pragma unroll
        for (int c = 0; c < 4; c++) acc[p][c] = 0ull;

#pragma unroll 4
    for (int d = 0; d < DD; d++) {
        const float* qb = qsT + d*128 + rg*8;
        ulonglong2 qa = *(const ulonglong2*)(qb);
        ulonglong2 qc = *(const ulonglong2*)(qb + 4);
        float4 w = *(const float4*)(ws + d*64 + cg*4);
        ull w0 = pk2(w.x, w.x), w1 = pk2(w.y, w.y);
        ull w2 = pk2(w.z, w.z), w3 = pk2(w.w, w.w);
        fma2(acc[0][0], qa.x, w0); fma2(acc[0][1], qa.x, w1);
        fma2(acc[0][2], qa.x, w2); fma2(acc[0][3], qa.x, w3);
        fma2(acc[1][0], qa.y, w0); fma2(acc[1][1], qa.y, w1);
        fma2(acc[1][2], qa.y, w2); fma2(acc[1][3], qa.y, w3);
        fma2(acc[2][0], qc.x, w0); fma2(acc[2][1], qc.x, w1);
        fma2(acc[2][2], qc.x, w2); fma2(acc[2][3], qc.x, w3);
        fma2(acc[3][0], qc.y, w0); fma2(acc[3][1], qc.y, w1);
        fma2(acc[3][2], qc.y, w2); fma2(acc[3][3], qc.y, w3);
    }

    float* outp;
    if      (job == 0) outp = g_Q;
    else if (job == 1) outp = g_K;
    else if (job == 2) outp = g_V;
    else               outp = g_EQ[job-3];

    const int gcol0 = ch*64 + cg*4;
    const int h  = gcol0 >> 4;
    const int k0 = gcol0 & 15;
#pragma unroll
    for (int p = 0; p < 4; p++) {
        float2 c0 = up2(acc[p][0]), c1 = up2(acc[p][1]);
        float2 c2 = up2(acc[p][2]), c3 = up2(acc[p][3]);
        int rlo = r0 + rg*8 + 2*p;
        if (rlo < nrows) {
            float* o = outp + ((size_t)h*nrows + rlo)*KDD + k0;
            *(float4*)o = make_float4(c0.x, c1.x, c2.x, c3.x);
        }
        if (rlo + 1 < nrows) {
            float* o = outp + ((size_t)h*nrows + rlo + 1)*KDD + k0;
            *(float4*)o = make_float4(c0.y, c1.y, c2.y, c3.y);
        }
    }
}

// ---------------------------------------------------------------------------
// Attention helpers. K/V row = 16 floats = 4 ulonglong2.
// ---------------------------------------------------------------------------
__device__ __forceinline__ float dotp(const ull* qp,
        ulonglong2 ka, ulonglong2 kb, ulonglong2 kc, ulonglong2 kd) {
    ull p0 = mul2(qp[0], ka.x);
    ull p1 = mul2(qp[1], ka.y);
    fma2(p0, qp[2], kb.x); fma2(p1, qp[3], kb.y);
    fma2(p0, qp[4], kc.x); fma2(p1, qp[5], kc.y);
    fma2(p0, qp[6], kd.x); fma2(p1, qp[7], kd.y);
    float2 s = up2(add2(p0, p1));
    return s.x + s.y;
}

__device__ __forceinline__ void accum(float w, ull* acc, float& l,
        ulonglong2 va, ulonglong2 vb, ulonglong2 vc, ulonglong2 vd) {
    l += w;
    ull wp = pk2(w, w);
    fma2(acc[0], wp, va.x); fma2(acc[1], wp, va.y);
    fma2(acc[2], wp, vb.x); fma2(acc[3], wp, vb.y);
    fma2(acc[4], wp, vc.x); fma2(acc[5], wp, vc.y);
    fma2(acc[6], wp, vd.x); fma2(acc[7], wp, vd.y);
}

// Merged base+extra key: one K/V read, two dots per query, ONE V accumulation
// with combined weight w = exp2(s_base) + exp2(s_extra).
__device__ __forceinline__ void attn_key_m(const ulonglong2* KsU, const ulonglong2* VsU,
        int j,
        const ull* qb0, const ull* qe0, bool ex0, float& l0, ull* acc0,
        const ull* qb1, const ull* qe1, bool ex1, float& l1, ull* acc1) {
    ulonglong2 ka = KsU[j*4+0], kb = KsU[j*4+1], kc = KsU[j*4+2], kd = KsU[j*4+3];
    float sb0 = dotp(qb0, ka, kb, kc, kd);
    float se0 = dotp(qe0, ka, kb, kc, kd);
    float sb1 = dotp(qb1, ka, kb, kc, kd);
    float se1 = dotp(qe1, ka, kb, kc, kd);
    float w0 = ex2(sb0) + (ex0 ? ex2(se0) : 0.f);
    float w1 = ex2(sb1) + (ex1 ? ex2(se1) : 0.f);
    ulonglong2 va = VsU[j*4+0], vb = VsU[j*4+1], vc = VsU[j*4+2], vd = VsU[j*4+3];
    accum(w0, acc0, l0, va, vb, vc, vd);
    accum(w1, acc1, l1, va, vb, vc, vd);
}

__device__ __forceinline__ void loadq(const float* src, ull* qp) {
    const float4* s4 = (const float4*)src;
#pragma unroll
    for (int t = 0; t < 4; t++) {
        float4 v = s4[t];
        qp[2*t]   = pk2(v.x*SCALE2, v.y*SCALE2);
        qp[2*t+1] = pk2(v.z*SCALE2, v.w*SCALE2);
    }
}

// ---------------------------------------------------------------------------
// Kernel 2: attention, merged base+extra passes, split over key HALVES.
// grid (HB=128, 2 qchunks, 2 halves), block 128, 2 queries/thread.
//  z=0: keys 0..250 (key 0 peeled base-only; keys 1..250 merged with
//       pick-key extras EQ1/EQ5) + paired del-query extra (EQ3, key 1+p)
//  z=1: keys 251..500 merged with del-key extras EQ2/EQ4
//       + paired pick-query extra (EQ0, key 251+p)
// ---------------------------------------------------------------------------
__global__ void __launch_bounds__(128, 3) attn_kernel() {
    extern __shared__ float sm[];
    const ulonglong2* KsU = (const ulonglong2*)sm;        // 251 rows * 4
    const ulonglong2* VsU = KsU + 251*4;

    const int hb  = blockIdx.x;
    const int tid = threadIdx.x;
    const int z   = blockIdx.z;
    const int gk0 = z ? 251 : 0;
    const int nk  = z ? 250 : 251;

    {
        const float4* K4 = (const float4*)(g_K + ((size_t)hb*GG + gk0)*KDD);
        const float4* V4 = (const float4*)(g_V + ((size_t)hb*GG + gk0)*KDD);
        float4* Ks4 = (float4*)sm;
        float4* Vs4 = Ks4 + 251*4;
        for (int i = tid; i < nk*4; i += 128) {
            Ks4[i] = K4[i];
            Vs4[i] = V4[i];
        }
    }
    __syncthreads();

    const int base = blockIdx.y * 256;
    const int n0 = base + tid;
    const int n1 = base + 128 + tid;
    const bool v0 = (n0 < GG);
    const bool v1 = (n1 < GG);
    const int nn0 = v0 ? n0 : 0;
    const int nn1 = v1 ? n1 : 0;

    ull qb0[8], qb1[8], qe0[8], qe1[8], acc0[8], acc1[8];
    float l0 = 0.f, l1 = 0.f;
#pragma unroll
    for (int k = 0; k < 8; k++) { acc0[k] = 0ull; acc1[k] = 0ull; }
    loadq(g_Q + ((size_t)hb*GG + nn0)*KDD, qb0);
    loadq(g_Q + ((size_t)hb*GG + nn1)*KDD, qb1);

    const bool pk0 = (n0 >= 1) && (n0 <= NPP);
    const bool dl0 = (n0 >= NPP+1) && (n0 < GG);
    const bool ex0 = pk0 || dl0;
    const int  p0  = pk0 ? (n0-1) : (dl0 ? (n0-NPP-1) : 0);
    const bool pk1 = (n1 >= 1) && (n1 <= NPP);
    const bool dl1 = (n1 >= NPP+1) && (n1 < GG);
    const bool ex1 = pk1 || dl1;
    const int  p1  = pk1 ? (n1-1) : (dl1 ? (n1-NPP-1) : 0);

    // extra-query vectors for this key-half (safe row 0 when !ex, gated later)
    {
        const float* e0src = z ? (pk0 ? g_EQ[2] : g_EQ[4]) : (pk0 ? g_EQ[1] : g_EQ[5]);
        const float* e1src = z ? (pk1 ? g_EQ[2] : g_EQ[4]) : (pk1 ? g_EQ[1] : g_EQ[5]);
        loadq(e0src + ((size_t)hb*NPP + p0)*KDD, qe0);
        loadq(e1src + ((size_t)hb*NPP + p1)*KDD, qe1);
    }

    if (z == 0) {
        // key 0: base only
        ulonglong2 ka = KsU[0], kb = KsU[1], kc = KsU[2], kd = KsU[3];
        float w0 = ex2(dotp(qb0, ka, kb, kc, kd));
        float w1 = ex2(dotp(qb1, ka, kb, kc, kd));
        ulonglong2 va = VsU[0], vb = VsU[1], vc = VsU[2], vd = VsU[3];
        accum(w0, acc0, l0, va, vb, vc, vd);
        accum(w1, acc1, l1, va, vb, vc, vd);
    }

    // merged loop: 250 keys
    const int jstart = (z == 0) ? 1 : 0;
    for (int jj = 0; jj < 250; jj++) {
        attn_key_m(KsU, VsU, jstart + jj,
                   qb0, qe0, ex0, l0, acc0,
                   qb1, qe1, ex1, l1, acc1);
    }

    // paired single extras (key lives in this half)
    {
        const bool c0 = z ? pk0 : dl0;
        const bool c1 = z ? pk1 : dl1;
        const float* psrc = z ? g_EQ[0] : g_EQ[3];
        if (c0) {
            int loc = z ? p0 : (1 + p0);
            loadq(psrc + ((size_t)hb*NPP + p0)*KDD, qe0);
            float w = ex2(dotp(qe0, KsU[loc*4+0], KsU[loc*4+1], KsU[loc*4+2], KsU[loc*4+3]));
            accum(w, acc0, l0, VsU[loc*4+0], VsU[loc*4+1], VsU[loc*4+2], VsU[loc*4+3]);
        }
        if (c1) {
            int loc = z ? p1 : (1 + p1);
            loadq(psrc + ((size_t)hb*NPP + p1)*KDD, qe1);
            float w = ex2(dotp(qe1, KsU[loc*4+0], KsU[loc*4+1], KsU[loc*4+2], KsU[loc*4+3]));
            accum(w, acc1, l1, VsU[loc*4+0], VsU[loc*4+1], VsU[loc*4+2], VsU[loc*4+3]);
        }
    }

    // store raw partials
    if (v0) {
        float4* o = (float4*)(g_pacc[z] + ((size_t)hb*GG + n0)*KDD);
#pragma unroll
        for (int t = 0; t < 4; t++) {
            float2 a0 = up2(acc0[2*t]);
            float2 a1 = up2(acc0[2*t+1]);
            o[t] = make_float4(a0.x, a0.y, a1.x, a1.y);
        }
        g_pl[z][(size_t)hb*GG + n0] = l0;
    }
    if (v1) {
        float4* o = (float4*)(g_pacc[z] + ((size_t)hb*GG + n1)*KDD);
#pragma unroll
        for (int t = 0; t < 4; t++) {
            float2 a0 = up2(acc1[2*t]);
            float2 a1 = up2(acc1[2*t+1]);
            o[t] = make_float4(a0.x, a0.y, a1.x, a1.y);
        }
        g_pl[z][(size_t)hb*GG + n1] = l1;
    }
}

// ---------------------------------------------------------------------------
// Kernel 3: combine 2 partials + normalize + output projection (R12 version).
// grid 126 (64-token tiles), block 256. Thread: 4 tokens x 8 e-cols.
// ---------------------------------------------------------------------------
__global__ void __launch_bounds__(256, 2) out_kernel(const float* __restrict__ Wout,
                                                     float* __restrict__ out) {
    extern __shared__ float sm[];
    float* hs   = sm;                    // 64 * 132
    float* ws   = sm + 64*132;           // 128 * 128
    float* sinv = ws + 128*128;          // 64 * 8

    const int tid = threadIdx.x;
    const int t0  = blockIdx.x * 64;

    {
        const float4* W4 = (const float4*)Wout;
        float4* ws4 = (float4*)ws;
        for (int i = tid; i < 128*32; i += 256) ws4[i] = W4[i];
    }
    for (int i = tid; i < 64*8; i += 256) {
        int t = i & 63, h = i >> 6;
        int tt = t0 + t;
        float l = 1.f;
        if (tt < NTOK) {
            size_t idx = (size_t)h*NTOK + tt;
            l = g_pl[0][idx] + g_pl[1][idx];
        }
        sinv[t*8 + h] = 1.0f / l;
    }
    __syncthreads();

    {
        const int t  = tid >> 2;     // 0..63
        const int k4 = tid & 3;      // 0..3
        const int tt = t0 + t;
#pragma unroll
        for (int h = 0; h < 8; h++) {
            float4 v = make_float4(0.f, 0.f, 0.f, 0.f);
            if (tt < NTOK) {
                size_t idx4 = (((size_t)h*NTOK + tt) << 2) + k4;
                float4 a = ((const float4*)g_pacc[0])[idx4];
                float4 b = ((const float4*)g_pacc[1])[idx4];
                float s = sinv[t*8 + h];
                v = make_float4((a.x+b.x)*s, (a.y+b.y)*s, (a.z+b.z)*s, (a.w+b.w)*s);
            }
            *(float4*)(hs + t*132 + h*16 + k4*4) = v;
        }
    }
    __syncthreads();

    const int eg = tid & 15;         // cols eg*8 .. +7
    const int tg = tid >> 4;         // 16 groups of 4 tokens
    const ulonglong2* wsU = (const ulonglong2*)ws;   // 32 per hk-row

    ull acc[4][4];
#pragma unroll
    for (int ti = 0; ti < 4; ti++)
#pragma unroll
        for (int c = 0; c < 4; c++) acc[ti][c] = 0ull;

#pragma unroll 4
    for (int hk = 0; hk < 128; hk++) {
        ulonglong2 wa = wsU[hk*32 + eg*2];
        ulonglong2 wb = wsU[hk*32 + eg*2 + 1];
        ull hb[4];
#pragma unroll
        for (int ti = 0; ti < 4; ti++) {
            float hv = hs[(tg*4 + ti)*132 + hk];
            hb[ti] = pk2(hv, hv);
        }
#pragma unroll
        for (int ti = 0; ti < 4; ti++) {
            fma2(acc[ti][0], hb[ti], wa.x);
            fma2(acc[ti][1], hb[ti], wa.y);
            fma2(acc[ti][2], hb[ti], wb.x);
            fma2(acc[ti][3], hb[ti], wb.y);
        }
    }

#pragma unroll
    for (int ti = 0; ti < 4; ti++) {
        int tt = t0 + tg*4 + ti;
        if (tt < NTOK) {
            float2 a0 = up2(acc[ti][0]), a1 = up2(acc[ti][1]);
            float2 a2 = up2(acc[ti][2]), a3 = up2(acc[ti][3]);
            float* o = out + (size_t)tt*EE + eg*8;
            *(float4*)(o)     = make_float4(a0.x, a0.y, a1.x, a1.y);
            *(float4*)(o + 4) = make_float4(a2.x, a2.y, a3.x, a3.y);
        }
    }
}

// ---------------------------------------------------------------------------
extern "C" void kernel_launch(void* const* d_in, const int* in_sizes, int n_in,
                              void* d_out, int out_size) {
    const float* q = (const float*)d_in[0];
    WArgs wa;
    for (int i = 0; i < 9; i++) wa.w[i] = (const float*)d_in[1 + i];
    const float* Wout = (const float*)d_in[10];
    float* out = (float*)d_out;

    const int projSmem = (128*128 + 128*64) * sizeof(float);        // 98304 B
    const int attnSmem = 251*KDD*2*sizeof(float);                   // 32128 B
    const int outSmem  = (64*132 + 128*128 + 64*8) * sizeof(float); // 101376 B
    cudaFuncSetAttribute(proj_kernel, cudaFuncAttributeMaxDynamicSharedMemorySize, projSmem);
    cudaFuncSetAttribute(attn_kernel, cudaFuncAttributeMaxDynamicSharedMemorySize, attnSmem);
    cudaFuncSetAttribute(out_kernel,  cudaFuncAttributeMaxDynamicSharedMemorySize, outSmem);

    transpose_kernel<<<dim3((NTOK + 31)/32, 4), dim3(32, 8)>>>(q);
    proj_kernel<<<dim3(381, 2), 256, projSmem>>>(wa);
    attn_kernel<<<dim3(HH*BB, 2, 2), 128, attnSmem>>>();
    out_kernel<<<(NTOK + 63)/64, 256, outSmem>>>(Wout, out);
}